// round 13
// baseline (speedup 1.0000x reference)
#include <cuda_runtime.h>
#include <math.h>

#define A_NUM 15
#define NUM_FG 128
#define RPN_BATCH_C 256
#define MAX_G 512
#define MAX_B 1024
#define TPB 512
#define NW (TPB / 32)
#define NP2 16

// Base anchors as compile-time constants (folded to immediates when unrolled)
__device__ constexpr float BAX1[15] = {-3.5f,-15.f,-38.f,-84.f,-176.f,  0.f, -8.f,-24.f,-56.f,-120.f,  2.5f, -3.f,-14.f,-36.f,-80.f};
__device__ constexpr float BAY1[15] = {  2.f, -4.f,-16.f,-40.f, -88.f,  0.f, -8.f,-24.f,-56.f,-120.f, -3.f,-14.f,-36.f,-80.f,-168.f};
__device__ constexpr float BAX2[15] = { 18.5f, 30.f, 53.f, 99.f, 191.f, 15.f, 23.f, 39.f, 71.f, 135.f, 12.5f, 18.f, 29.f, 51.f, 95.f};
__device__ constexpr float BAY2[15] = { 13.f, 19.f, 31.f, 55.f, 103.f, 15.f, 23.f, 39.f, 71.f, 135.f, 18.f, 29.f, 51.f, 95.f, 183.f};
__device__ constexpr float BAREA[15] = {276.f,1104.f,4416.f,17664.f,70656.f, 256.f,1024.f,4096.f,16384.f,65536.f, 242.f,968.f,3872.f,15488.f,61952.f};

// Same table in constant memory for runtime-indexed access (phase 1)
__constant__ float c_base[60] = {
    -3.5f,   2.f,  18.5f,  13.f,   -15.f,   -4.f,  30.f,   19.f,
   -38.f,  -16.f,  53.f,   31.f,   -84.f,  -40.f,  99.f,   55.f,
  -176.f,  -88.f, 191.f,  103.f,     0.f,    0.f,  15.f,   15.f,
    -8.f,   -8.f,  23.f,   23.f,   -24.f,  -24.f,  39.f,   39.f,
   -56.f,  -56.f,  71.f,   71.f,  -120.f, -120.f, 135.f,  135.f,
     2.5f,  -3.f,  12.5f,  18.f,    -3.f,  -14.f,  18.f,   29.f,
   -14.f,  -36.f,  29.f,   51.f,   -36.f,  -80.f,  51.f,   95.f,
   -80.f, -168.f,  95.f,  183.f
};

__device__ int g_bp[MAX_B];
__device__ int g_bn[MAX_B];
__device__ int g_win[MAX_G];
__device__ int g_kfirst = 0x7fffffff;          // first inside anchor (global)
__device__ unsigned g_bar_count = 0;
__device__ volatile unsigned g_bar_gen = 0;

// Software grid barrier. Valid: all blocks co-resident (grid = 2 * #SMs, occ 2).
__device__ __forceinline__ void grid_barrier(int nblocks) {
    __syncthreads();
    if (threadIdx.x == 0) {
        __threadfence();
        unsigned gen = g_bar_gen;
        if (atomicAdd(&g_bar_count, 1u) == (unsigned)(nblocks - 1)) {
            atomicExch(&g_bar_count, 0u);
            __threadfence();
            g_bar_gen = gen + 1;
        } else {
            while (g_bar_gen == gen) { }
        }
        __threadfence();
    }
    __syncthreads();
}

__global__ void __launch_bounds__(TPB, 2)
k_fused(const float* __restrict__ gt, const float* __restrict__ meta,
        float* __restrict__ out, int K, int r, int c, int G,
        int nblocks, int nP1, int chunk, float inv_c) {
    __shared__ float4 s_gt[MAX_G];
    __shared__ float  s_area[MAX_G];
    __shared__ int    s_wp[NW], s_wn[NW];
    __shared__ float  s_ri[NW], s_rd[NW];
    __shared__ int    s_rk[NW];
    __shared__ int    s_sp[TPB], s_sn[TPB];

    const int tid  = threadIdx.x;
    const int bid  = blockIdx.x;
    const int lane = tid & 31;
    const int warp = tid >> 5;
    const unsigned FULL = 0xffffffffu;

    for (int g = tid; g < G; g += TPB) {
        float4 b = reinterpret_cast<const float4*>(gt)[g];
        s_gt[g] = b;
        s_area[g] = (b.z - b.x + 1.0f) * (b.w - b.y + 1.0f);
    }
    __syncthreads();

    const float h = meta[0], w = meta[1];
    const float wm1 = w - 1.f, hm1 = h - 1.f;
    float*  lab = out + (size_t)8 * K;
    float4* tgt = reinterpret_cast<float4*>(out + (size_t)4 * K);

    const bool isP1 = (bid < nP1);
    const int base = isP1 ? bid * chunk : 0;
    const int end  = isP1 ? min(base + chunk, K) : 0;
    const float4 gb0 = s_gt[0];

    if (isP1) {
        // ============ Phase 1: per-anchor labels / targets / anchors ======
        for (int sb = base; sb < end; sb += TPB) {
            int k = sb + tid;
            int kk = min(k, end - 1);
            // kk/15 and t2/c via verified float-reciprocal (no int division)
            int t2 = (int)(((float)kk + 0.5f) * (1.0f / 15.0f));
            int a  = kk - t2 * A_NUM;
            int ii = (int)(((float)t2 + 0.5f) * inv_c);
            int jj = t2 - ii * c;
            float sx = (float)(jj << 4);
            float sy = (float)(ii << 4);

            // per-warp spatial window
            float sxlo = sx, sxhi = sx, sylo = sy, syhi = sy;
            #pragma unroll
            for (int off = 16; off; off >>= 1) {
                sxlo = fminf(sxlo, __shfl_xor_sync(FULL, sxlo, off));
                sxhi = fmaxf(sxhi, __shfl_xor_sync(FULL, sxhi, off));
                sylo = fminf(sylo, __shfl_xor_sync(FULL, sylo, off));
                syhi = fmaxf(syhi, __shfl_xor_sync(FULL, syhi, off));
            }
            float xlo = sxlo - 178.f, xhi = sxhi + 193.f;
            float ylo = sylo - 170.f, yhi = syhi + 185.f;

            float x1 = sx + c_base[a * 4 + 0];
            float y1 = sy + c_base[a * 4 + 1];
            float x2 = sx + c_base[a * 4 + 2];
            float y2 = sy + c_base[a * 4 + 3];

            bool valid  = (k < end);
            bool inside = (x1 >= 0.f) && (y1 >= 0.f) && (x2 < w) && (y2 < h);
            bool need   = inside && valid;

            if (valid)
                reinterpret_cast<float4*>(out)[k] = make_float4(x1, y1, x2, y2);

            // global first-inside-anchor (one atomic per warp-pass)
            {
                unsigned im = __ballot_sync(FULL, need);
                if (im && lane == (unsigned)(__ffs(im) - 1))
                    atomicMin(&g_kfirst, k);
            }

            // inside anchors are unclipped; clip is identity here
            float cx1 = fminf(fmaxf(x1, 0.f), wm1);
            float cy1 = fminf(fmaxf(y1, 0.f), hm1);
            float cx2 = fminf(fmaxf(x2, 0.f), wm1);
            float cy2 = fminf(fmaxf(y2, 0.f), hm1);
            float areaA = (cx2 - cx1 + 1.f) * (cy2 - cy1 + 1.f);

            // dual accumulators (even/odd candidates) to halve the carried chain
            float bi0 = 0.f, bd0 = 1.f, bi1 = 0.f, bd1 = 1.f;
            int   bg0 = -1,  bg1 = -1;

            if (__any_sync(FULL, need)) {
                for (int gbs = 0; gbs < G; gbs += 32) {
                    int g = gbs + lane;
                    float4 b; float ar = 0.f;
                    bool ok = false;
                    if (g < G) {
                        b = s_gt[g]; ar = s_area[g];
                        ok = (b.y <= yhi) && (b.w >= ylo) && (b.x <= xhi) && (b.z >= xlo);
                    }
                    unsigned m = __ballot_sync(FULL, ok);
                    while (m) {
                        int s0 = __ffs(m) - 1;
                        m &= m - 1;
                        bool has1 = (m != 0);
                        int s1 = has1 ? (__ffs(m) - 1) : s0;
                        if (has1) m &= m - 1;

                        float ax = __shfl_sync(FULL, b.x, s0);
                        float ay = __shfl_sync(FULL, b.y, s0);
                        float az = __shfl_sync(FULL, b.z, s0);
                        float aw = __shfl_sync(FULL, b.w, s0);
                        float aa = __shfl_sync(FULL, ar,  s0);
                        float ex = __shfl_sync(FULL, b.x, s1);
                        float ey = __shfl_sync(FULL, b.y, s1);
                        float ez = __shfl_sync(FULL, b.z, s1);
                        float ew2 = __shfl_sync(FULL, b.w, s1);
                        float ea = __shfl_sync(FULL, ar,  s1);

                        float iwA = (fminf(cx2, az) - fmaxf(cx1, ax)) + 1.f;
                        float ihA = (fminf(cy2, aw) - fmaxf(cy1, ay)) + 1.f;
                        float inA = fmaxf(iwA, 0.f) * fmaxf(ihA, 0.f);
                        float dnA = (areaA + aa) - inA;
                        if (inA * bd0 > bi0 * dnA) { bi0 = inA; bd0 = dnA; bg0 = gbs + s0; }

                        float iwB = (fminf(cx2, ez) - fmaxf(cx1, ex)) + 1.f;
                        float ihB = (fminf(cy2, ew2) - fmaxf(cy1, ey)) + 1.f;
                        float inB = fmaxf(iwB, 0.f) * fmaxf(ihB, 0.f);
                        float dnB = (areaA + ea) - inB;
                        if (has1 && inB * bd1 > bi1 * dnB) { bi1 = inB; bd1 = dnB; bg1 = gbs + s1; }
                    }
                }
            }

            // merge odd into even (prefer smaller g on exact tie)
            {
                float p1 = bi1 * bd0, p2 = bi0 * bd1;
                if (p1 > p2 || (p1 == p2 && (unsigned)bg1 < (unsigned)bg0)) {
                    bi0 = bi1; bd0 = bd1; bg0 = bg1;
                }
            }

            if (!valid) continue;
            if (!inside) {
                tgt[k] = make_float4(0.f, 0.f, 0.f, 0.f);
                lab[k] = -1.f;
                continue;
            }

            float mo = __fdiv_rn(bi0, bd0);   // exact: feeds label thresholds
            float l = -1.f;
            if (mo < 0.3f)  l = 0.f;
            if (mo >= 0.7f) l = 1.f;
            lab[k] = l;

            float4 gb = (bg0 >= 0) ? s_gt[bg0] : gb0;
            float ew = cx2 - cx1 + 1.f, eh = cy2 - cy1 + 1.f;
            float ecx = cx1 + 0.5f * ew, ecy = cy1 + 0.5f * eh;
            float gw = gb.z - gb.x + 1.f, gh = gb.w - gb.y + 1.f;
            float gcx = gb.x + 0.5f * gw, gcy = gb.y + 0.5f * gh;
            tgt[k] = make_float4(__fdividef(gcx - ecx, ew),
                                 __fdividef(gcy - ecy, eh),
                                 __logf(__fdividef(gw, ew)),
                                 __logf(__fdividef(gh, eh)));
        }
    } else {
        // ======== Phase 2 (concurrent): per-gt argmax, per-shape windows ==
        for (int g = bid - nP1; g < G; g += NP2) {
            float4 b = s_gt[g];
            float areaB = s_area[g];

            // only positive-intersection inside anchors can win; ties -> min k
            float bi = 0.f, bd = 1.f;
            int   bk = 0x7fffffff;

            #pragma unroll
            for (int a = 0; a < A_NUM; a++) {
                // shape-exact window: intersection>0 AND inside image
                float sxmin = fmaxf(-BAX1[a], b.x - BAX2[a] - 1.f);
                float sxmax = fminf(w - BAX2[a], b.z - BAX1[a] + 1.f);
                float symin = fmaxf(-BAY1[a], b.y - BAY2[a] - 1.f);
                float symax = fminf(h - BAY2[a], b.w - BAY1[a] + 1.f);
                int j0 = max(0, (int)ceilf(sxmin * 0.0625f));
                int j1 = min(c - 1, (int)floorf(sxmax * 0.0625f));
                int i0 = max(0, (int)ceilf(symin * 0.0625f));
                int i1 = min(r - 1, (int)floorf(symax * 0.0625f));
                int nx = j1 - j0 + 1;
                int ny = i1 - i0 + 1;
                if (nx <= 0 || ny <= 0) continue;
                int ncell = nx * ny;
                float inv_nx = 1.0f / (float)nx;

                for (int t = tid; t < ncell; t += TPB) {
                    int dv = (int)(((float)t + 0.5f) * inv_nx);
                    int jj = j0 + (t - dv * nx);
                    int ii = i0 + dv;
                    float sx = (float)(jj << 4);
                    float sy = (float)(ii << 4);
                    float x1 = sx + BAX1[a];
                    float y1 = sy + BAY1[a];
                    float x2 = sx + BAX2[a];
                    float y2 = sy + BAY2[a];
                    bool ins = (x1 >= 0.f) && (y1 >= 0.f) && (x2 < w) && (y2 < h);
                    float iw = (fminf(x2, b.z) - fmaxf(x1, b.x)) + 1.f;
                    float ih = (fminf(y2, b.w) - fmaxf(y1, b.y)) + 1.f;
                    float inter = fmaxf(iw, 0.f) * fmaxf(ih, 0.f);
                    float denom = (BAREA[a] + areaB) - inter;
                    int k = (ii * c + jj) * A_NUM + a;
                    float p1 = inter * bd, p2 = bi * denom;
                    // strict: zero-inter never taken (bi starts at 0)
                    if (ins && (p1 > p2 || (p1 == p2 && bi > 0.f && k < bk))) {
                        bi = inter; bd = denom; bk = k;
                    }
                }
            }

            #pragma unroll
            for (int off = 16; off; off >>= 1) {
                float oi = __shfl_down_sync(FULL, bi, off);
                float od = __shfl_down_sync(FULL, bd, off);
                int   ok = __shfl_down_sync(FULL, bk, off);
                float p1 = oi * bd, p2 = bi * od;
                if (p1 > p2 || (p1 == p2 && oi > 0.f && ok < bk)) { bi = oi; bd = od; bk = ok; }
            }
            if (lane == 0) { s_ri[warp] = bi; s_rd[warp] = bd; s_rk[warp] = bk; }
            __syncthreads();
            if (warp == 0) {
                bi = (lane < NW) ? s_ri[lane] : 0.f;
                bd = (lane < NW) ? s_rd[lane] : 1.f;
                bk = (lane < NW) ? s_rk[lane] : 0x7fffffff;
                #pragma unroll
                for (int off = 16; off; off >>= 1) {
                    float oi = __shfl_down_sync(FULL, bi, off);
                    float od = __shfl_down_sync(FULL, bd, off);
                    int   ok = __shfl_down_sync(FULL, bk, off);
                    float p1 = oi * bd, p2 = bi * od;
                    if (p1 > p2 || (p1 == p2 && oi > 0.f && ok < bk)) { bi = oi; bd = od; bk = ok; }
                }
                if (lane == 0) g_win[g] = bk;   // tid 0: ordered by barrier fence
            }
            __syncthreads();
        }
    }

    grid_barrier(nblocks);

    if (isP1) {
        // ---- apply winners that fall in my chunk, then count -------------
        {
            int kfirst = __ldcg(&g_kfirst);
            if (tid < G) {
                int kw = __ldcg(&g_win[tid]);
                if (kw == 0x7fffffff) kw = kfirst;   // all-zero gt column
                if (kw >= base && kw < end) lab[kw] = 1.0f;
            }
        }
        __syncthreads();

        int cp = 0, cn = 0;
        for (int k = base + tid; k < end; k += TPB) {
            float l = lab[k];               // all writes here were by this block
            cp += (l == 1.f);
            cn += (l == 0.f);
        }
        #pragma unroll
        for (int off = 16; off; off >>= 1) {
            cp += __shfl_down_sync(FULL, cp, off);
            cn += __shfl_down_sync(FULL, cn, off);
        }
        if (lane == 0) { s_wp[warp] = cp; s_wn[warp] = cn; }
        __syncthreads();
        if (tid == 0) {
            int p = 0, n = 0;
            #pragma unroll
            for (int v = 0; v < NW; v++) { p += s_wp[v]; n += s_wn[v]; }
            g_bp[bid] = p; g_bn[bid] = n;
        }
    }

    grid_barrier(nblocks);
    if (!isP1) return;

    // ---- shfl-based scan of block counts + apply subsampling -------------
    int vp = (tid < nP1) ? __ldcg(&g_bp[tid]) : 0;
    int vn = (tid < nP1) ? __ldcg(&g_bn[tid]) : 0;
    #pragma unroll
    for (int off = 1; off < 32; off <<= 1) {
        int tp = __shfl_up_sync(FULL, vp, off);
        int tn = __shfl_up_sync(FULL, vn, off);
        if (lane >= off) { vp += tp; vn += tn; }
    }
    if (lane == 31) { s_wp[warp] = vp; s_wn[warp] = vn; }
    __syncthreads();
    if (warp == 0 && lane < NW) {
        int wv = s_wp[lane], wn2 = s_wn[lane];
        #pragma unroll
        for (int off = 1; off < NW; off <<= 1) {
            int tp = __shfl_up_sync(0xffffu, wv, off);
            int tn = __shfl_up_sync(0xffffu, wn2, off);
            if (lane >= off) { wv += tp; wn2 += tn; }
        }
        s_wp[lane] = wv; s_wn[lane] = wn2;
    }
    __syncthreads();
    if (warp > 0) { vp += s_wp[warp - 1]; vn += s_wn[warp - 1]; }
    s_sp[tid] = vp; s_sn[tid] = vn;
    __syncthreads();

    int runP = (bid > 0) ? s_sp[bid - 1] : 0;
    int runN = (bid > 0) ? s_sn[bid - 1] : 0;
    int totP = s_sp[nP1 - 1];
    const int numBg = RPN_BATCH_C - (totP < NUM_FG ? totP : NUM_FG);
    __syncthreads();

    for (int s = base; s < end; s += TPB) {
        int k = s + tid;
        float l = (k < end) ? lab[k] : -1.f;
        int pos = (l == 1.f);
        int neg = (l == 0.f);
        unsigned ballp = __ballot_sync(FULL, pos);
        unsigned balln = __ballot_sync(FULL, neg);
        if (lane == 0) { s_wp[warp] = __popc(ballp); s_wn[warp] = __popc(balln); }
        __syncthreads();
        int wp = 0, wn = 0, totPb = 0, totNb = 0;
        #pragma unroll
        for (int v = 0; v < NW; v++) {
            int a2 = s_wp[v], b2 = s_wn[v];
            if (v < warp) { wp += a2; wn += b2; }
            totPb += a2; totNb += b2;
        }
        unsigned lm = (1u << lane) - 1u;
        int rp = runP + wp + __popc(ballp & lm) + 1;
        int rn = runN + wn + __popc(balln & lm) + 1;
        if (k < end) {
            if (pos && rp > NUM_FG) lab[k] = -1.f;
            if (neg && rn > numBg)  lab[k] = -1.f;
        }
        runP += totPb; runN += totNb;
        __syncthreads();
    }
}

// ---------------------------------------------------------------------------
extern "C" void kernel_launch(void* const* d_in, const int* in_sizes, int n_in,
                              void* d_out, int out_size) {
    const float* gt   = (const float*)d_in[0];
    const float* meta = (const float*)d_in[1];
    float* out = (float*)d_out;

    int G = in_sizes[0] / 4;
    if (G > MAX_G) G = MAX_G;
    int K  = in_sizes[2];
    int rc = K / A_NUM;
    int c  = (int)(sqrt((double)rc) + 0.5);
    int r  = rc / c;
    float inv_c = (float)(1.0 / (double)c);

    int dev = 0;
    cudaGetDevice(&dev);
    int nsm = 0;
    cudaDeviceGetAttribute(&nsm, cudaDevAttrMultiProcessorCount, dev);
    if (nsm <= 0) nsm = 148;
    int nblocks = 2 * nsm;               // 2 co-resident blocks per SM
    if (nblocks > MAX_B) nblocks = MAX_B;
    if (nblocks > TPB) nblocks = TPB;    // scan capacity
    int nP1 = nblocks - NP2;             // 16 blocks handle all gts
    int chunk = (K + nP1 - 1) / nP1;

    k_fused<<<nblocks, TPB>>>(gt, meta, out, K, r, c, G, nblocks, nP1, chunk, inv_c);
}

// round 15
// speedup vs baseline: 1.9390x; 1.9390x over previous
#include <cuda_runtime.h>
#include <math.h>

#define A_NUM 15
#define NUM_FG 128
#define RPN_BATCH_C 256
#define MAX_G 512
#define MAX_P1 512
#define TPB 512
#define NW (TPB / 32)

// Base anchors as compile-time constants (folded to immediates when unrolled)
__device__ constexpr float BAX1[15] = {-3.5f,-15.f,-38.f,-84.f,-176.f,  0.f, -8.f,-24.f,-56.f,-120.f,  2.5f, -3.f,-14.f,-36.f,-80.f};
__device__ constexpr float BAY1[15] = {  2.f, -4.f,-16.f,-40.f, -88.f,  0.f, -8.f,-24.f,-56.f,-120.f, -3.f,-14.f,-36.f,-80.f,-168.f};
__device__ constexpr float BAX2[15] = { 18.5f, 30.f, 53.f, 99.f, 191.f, 15.f, 23.f, 39.f, 71.f, 135.f, 12.5f, 18.f, 29.f, 51.f, 95.f};
__device__ constexpr float BAY2[15] = { 13.f, 19.f, 31.f, 55.f, 103.f, 15.f, 23.f, 39.f, 71.f, 135.f, 18.f, 29.f, 51.f, 95.f, 183.f};
__device__ constexpr float BAREA[15] = {276.f,1104.f,4416.f,17664.f,70656.f, 256.f,1024.f,4096.f,16384.f,65536.f, 242.f,968.f,3872.f,15488.f,61952.f};

// Same table in constant memory for runtime-indexed access (phase 1)
__constant__ float c_base[60] = {
    -3.5f,   2.f,  18.5f,  13.f,   -15.f,   -4.f,  30.f,   19.f,
   -38.f,  -16.f,  53.f,   31.f,   -84.f,  -40.f,  99.f,   55.f,
  -176.f,  -88.f, 191.f,  103.f,     0.f,    0.f,  15.f,   15.f,
    -8.f,   -8.f,  23.f,   23.f,   -24.f,  -24.f,  39.f,   39.f,
   -56.f,  -56.f,  71.f,   71.f,  -120.f, -120.f, 135.f,  135.f,
     2.5f,  -3.f,  12.5f,  18.f,    -3.f,  -14.f,  18.f,   29.f,
   -14.f,  -36.f,  29.f,   51.f,   -36.f,  -80.f,  51.f,   95.f,
   -80.f, -168.f,  95.f,  183.f
};

__device__ int g_bp[MAX_P1];
__device__ int g_bn[MAX_P1];
__device__ int g_win[MAX_G];
__device__ unsigned g_bar_count = 0;
__device__ volatile unsigned g_bar_gen = 0;

// Software grid barrier. Valid: all blocks co-resident (grid = 2 * #SMs, occ 2).
__device__ __forceinline__ void grid_barrier(int nblocks) {
    __syncthreads();
    if (threadIdx.x == 0) {
        __threadfence();
        unsigned gen = g_bar_gen;
        if (atomicAdd(&g_bar_count, 1u) == (unsigned)(nblocks - 1)) {
            atomicExch(&g_bar_count, 0u);
            __threadfence();
            g_bar_gen = gen + 1;
        } else {
            while (g_bar_gen == gen) { }
        }
        __threadfence();
    }
    __syncthreads();
}

__global__ void __launch_bounds__(TPB, 2)
k_fused(const float* __restrict__ gt, const float* __restrict__ meta,
        float* __restrict__ out, int K, int r, int c, int G,
        int nblocks, int nP1, int chunk, float inv_c) {
    __shared__ float4 s_gt[MAX_G];
    __shared__ float  s_area[MAX_G];
    __shared__ int    s_wp[NW], s_wn[NW];
    __shared__ float  s_ri[NW], s_rd[NW];
    __shared__ int    s_rk[NW];
    __shared__ int    s_sp[MAX_P1], s_sn[MAX_P1];

    const int tid  = threadIdx.x;
    const int bid  = blockIdx.x;
    const int lane = tid & 31;
    const int warp = tid >> 5;
    const unsigned FULL = 0xffffffffu;

    for (int g = tid; g < G; g += TPB) {
        float4 b = reinterpret_cast<const float4*>(gt)[g];
        s_gt[g] = b;
        s_area[g] = (b.z - b.x + 1.0f) * (b.w - b.y + 1.0f);
    }
    __syncthreads();

    const float h = meta[0], w = meta[1];
    const float wm1 = w - 1.f, hm1 = h - 1.f;
    float*  lab = out + (size_t)8 * K;
    float4* tgt = reinterpret_cast<float4*>(out + (size_t)4 * K);

    const bool isP1 = (bid < nP1);
    const int base = isP1 ? bid * chunk : 0;
    const int end  = isP1 ? min(base + chunk, K) : 0;
    const float4 gb0 = s_gt[0];

    if (isP1) {
        // ============ Phase 1: per-anchor labels / targets / anchors ======
        for (int sb = base; sb < end; sb += TPB) {
            int k = sb + tid;
            int kk = min(k, end - 1);
            // kk/15 and t2/c via verified float-reciprocal (no int division)
            int t2 = (int)(((float)kk + 0.5f) * (1.0f / 15.0f));
            int a  = kk - t2 * A_NUM;
            int ii = (int)(((float)t2 + 0.5f) * inv_c);
            int jj = t2 - ii * c;
            float sx = (float)(jj << 4);
            float sy = (float)(ii << 4);

            // per-warp spatial window
            float sxlo = sx, sxhi = sx, sylo = sy, syhi = sy;
            #pragma unroll
            for (int off = 16; off; off >>= 1) {
                sxlo = fminf(sxlo, __shfl_xor_sync(FULL, sxlo, off));
                sxhi = fmaxf(sxhi, __shfl_xor_sync(FULL, sxhi, off));
                sylo = fminf(sylo, __shfl_xor_sync(FULL, sylo, off));
                syhi = fmaxf(syhi, __shfl_xor_sync(FULL, syhi, off));
            }
            float xlo = sxlo - 178.f, xhi = sxhi + 193.f;
            float ylo = sylo - 170.f, yhi = syhi + 185.f;

            float x1 = sx + c_base[a * 4 + 0];
            float y1 = sy + c_base[a * 4 + 1];
            float x2 = sx + c_base[a * 4 + 2];
            float y2 = sy + c_base[a * 4 + 3];

            bool valid  = (k < end);
            bool inside = (x1 >= 0.f) && (y1 >= 0.f) && (x2 < w) && (y2 < h);
            bool need   = inside && valid;

            if (valid)
                reinterpret_cast<float4*>(out)[k] = make_float4(x1, y1, x2, y2);

            // inside anchors are unclipped; clip is identity here
            float cx1 = fminf(fmaxf(x1, 0.f), wm1);
            float cy1 = fminf(fmaxf(y1, 0.f), hm1);
            float cx2 = fminf(fmaxf(x2, 0.f), wm1);
            float cy2 = fminf(fmaxf(y2, 0.f), hm1);
            float areaA = (cx2 - cx1 + 1.f) * (cy2 - cy1 + 1.f);

            float bi = 0.f, bd = 1.f;     // matches "all-zero row -> argmax 0"
            int   bg = -1;

            if (__any_sync(FULL, need)) {
                for (int gbs = 0; gbs < G; gbs += 32) {
                    int g = gbs + lane;
                    bool ok = false;
                    if (g < G) {
                        float4 b = s_gt[g];
                        ok = (b.y <= yhi) && (b.w >= ylo) && (b.x <= xhi) && (b.z >= xlo);
                    }
                    unsigned m = __ballot_sync(FULL, ok);
                    while (m) {
                        int src = __ffs(m) - 1;
                        m &= m - 1;
                        int gc = gbs + src;
                        // uniform address -> broadcast LDS (conflict-free),
                        // replaces 5 SHFLs on the MIO pipe with 2 loads
                        float4 bb = s_gt[gc];
                        float  ba = s_area[gc];
                        float iw = (fminf(cx2, bb.z) - fmaxf(cx1, bb.x)) + 1.f;
                        float ih = (fminf(cy2, bb.w) - fmaxf(cy1, bb.y)) + 1.f;
                        float inter = fmaxf(iw, 0.f) * fmaxf(ih, 0.f);
                        float denom = (areaA + ba) - inter;
                        // per-anchor running max (cross-multiplication, exact)
                        if (inter * bd > bi * denom) {
                            bi = inter; bd = denom; bg = gc;
                        }
                    }
                }
            }

            if (!valid) continue;
            if (!inside) {
                tgt[k] = make_float4(0.f, 0.f, 0.f, 0.f);
                lab[k] = -1.f;
                continue;
            }

            float mo = __fdiv_rn(bi, bd);   // exact: feeds label thresholds
            float l = -1.f;
            if (mo < 0.3f)  l = 0.f;
            if (mo >= 0.7f) l = 1.f;
            lab[k] = l;

            float4 gb = (bg >= 0) ? s_gt[bg] : gb0;
            float ew = cx2 - cx1 + 1.f, eh = cy2 - cy1 + 1.f;
            float ecx = cx1 + 0.5f * ew, ecy = cy1 + 0.5f * eh;
            float gw = gb.z - gb.x + 1.f, gh = gb.w - gb.y + 1.f;
            float gcx = gb.x + 0.5f * gw, gcy = gb.y + 0.5f * gh;
            tgt[k] = make_float4(__fdividef(gcx - ecx, ew),
                                 __fdividef(gcy - ecy, eh),
                                 __logf(__fdividef(gw, ew)),
                                 __logf(__fdividef(gh, eh)));
        }
    } else {
        // ============ Phase 2 (concurrent): per-gt argmax ================
        for (int g = bid - nP1; g < G; g += nblocks - nP1) {
            float4 b = s_gt[g];
            float areaB = s_area[g];

            int j0 = max(0,     (int)floorf((b.x - 193.f) * 0.0625f) - 1);
            int j1 = min(c - 1, (int)ceilf ((b.z + 178.f) * 0.0625f) + 1);
            int i0 = max(0,     (int)floorf((b.y - 185.f) * 0.0625f) - 1);
            int i1 = min(r - 1, (int)ceilf ((b.w + 170.f) * 0.0625f) + 1);
            int nj = j1 - j0 + 1;
            int ncells = nj * (i1 - i0 + 1);
            float inv_nj = 1.0f / (float)nj;   // full-precision, once per gt

            float bi = -1.f, bd = 1.f;
            int   bk = 0x7fffffff;

            for (int t = tid; t < ncells; t += TPB) {
                int dv = (int)(((float)t + 0.5f) * inv_nj);
                int jj = j0 + (t - dv * nj);
                int ii = i0 + dv;
                float sx = (float)(jj << 4);
                float sy = (float)(ii << 4);
                int kbase = (ii * c + jj) * A_NUM;
                #pragma unroll
                for (int a = 0; a < A_NUM; a++) {
                    float x1 = sx + BAX1[a];
                    float y1 = sy + BAY1[a];
                    float x2 = sx + BAX2[a];
                    float y2 = sy + BAY2[a];
                    bool ins = (x1 >= 0.f) && (y1 >= 0.f) && (x2 < w) && (y2 < h);
                    float iw = (fminf(x2, b.z) - fmaxf(x1, b.x)) + 1.f;
                    float ih = (fminf(y2, b.w) - fmaxf(y1, b.y)) + 1.f;
                    float inter = fmaxf(iw, 0.f) * fmaxf(ih, 0.f);
                    float denom = (BAREA[a] + areaB) - inter;
                    int k = kbase + a;
                    float p1 = inter * bd, p2 = bi * denom;
                    if (ins && (p1 > p2 || (p1 == p2 && k < bk))) {
                        bi = inter; bd = denom; bk = k;
                    }
                }
            }

            #pragma unroll
            for (int off = 16; off; off >>= 1) {
                float oi = __shfl_down_sync(FULL, bi, off);
                float od = __shfl_down_sync(FULL, bd, off);
                int   ok = __shfl_down_sync(FULL, bk, off);
                float p1 = oi * bd, p2 = bi * od;
                if (p1 > p2 || (p1 == p2 && ok < bk)) { bi = oi; bd = od; bk = ok; }
            }
            if (lane == 0) { s_ri[warp] = bi; s_rd[warp] = bd; s_rk[warp] = bk; }
            __syncthreads();
            if (warp == 0) {
                bi = (lane < NW) ? s_ri[lane] : -1.f;
                bd = (lane < NW) ? s_rd[lane] : 1.f;
                bk = (lane < NW) ? s_rk[lane] : 0x7fffffff;
                #pragma unroll
                for (int off = 16; off; off >>= 1) {
                    float oi = __shfl_down_sync(FULL, bi, off);
                    float od = __shfl_down_sync(FULL, bd, off);
                    int   ok = __shfl_down_sync(FULL, bk, off);
                    float p1 = oi * bd, p2 = bi * od;
                    if (p1 > p2 || (p1 == p2 && ok < bk)) { bi = oi; bd = od; bk = ok; }
                }
                if (lane == 0) g_win[g] = bk;   // ordered by barrier fence
            }
            __syncthreads();
        }
    }

    grid_barrier(nblocks);

    if (isP1) {
        // ---- apply winners that fall in my chunk, then count -------------
        if (tid < G) {
            int kw = __ldcg(&g_win[tid]);
            if (kw >= base && kw < end) lab[kw] = 1.0f;
        }
        __syncthreads();

        int cp = 0, cn = 0;
        for (int k = base + tid; k < end; k += TPB) {
            float l = lab[k];               // own block wrote everything here
            cp += (l == 1.f);
            cn += (l == 0.f);
        }
        #pragma unroll
        for (int off = 16; off; off >>= 1) {
            cp += __shfl_down_sync(FULL, cp, off);
            cn += __shfl_down_sync(FULL, cn, off);
        }
        if (lane == 0) { s_wp[warp] = cp; s_wn[warp] = cn; }
        __syncthreads();
        if (tid == 0) {
            int p = 0, n = 0;
            #pragma unroll
            for (int v = 0; v < NW; v++) { p += s_wp[v]; n += s_wn[v]; }
            g_bp[bid] = p; g_bn[bid] = n;
        }
    }

    grid_barrier(nblocks);
    if (!isP1) return;

    // ---- shfl-based scan of block counts + apply subsampling -------------
    int vp = (tid < nP1) ? __ldcg(&g_bp[tid]) : 0;
    int vn = (tid < nP1) ? __ldcg(&g_bn[tid]) : 0;
    #pragma unroll
    for (int off = 1; off < 32; off <<= 1) {
        int tp = __shfl_up_sync(FULL, vp, off);
        int tn = __shfl_up_sync(FULL, vn, off);
        if (lane >= off) { vp += tp; vn += tn; }
    }
    if (lane == 31) { s_wp[warp] = vp; s_wn[warp] = vn; }
    __syncthreads();
    if (warp == 0 && lane < NW) {
        int wv = s_wp[lane], wn2 = s_wn[lane];
        #pragma unroll
        for (int off = 1; off < NW; off <<= 1) {
            int tp = __shfl_up_sync(0xffffu, wv, off);
            int tn = __shfl_up_sync(0xffffu, wn2, off);
            if (lane >= off) { wv += tp; wn2 += tn; }
        }
        s_wp[lane] = wv; s_wn[lane] = wn2;
    }
    __syncthreads();
    if (warp > 0) { vp += s_wp[warp - 1]; vn += s_wn[warp - 1]; }
    s_sp[tid] = vp; s_sn[tid] = vn;
    __syncthreads();

    int runP = (bid > 0) ? s_sp[bid - 1] : 0;
    int runN = (bid > 0) ? s_sn[bid - 1] : 0;
    int totP = s_sp[nP1 - 1];
    const int numBg = RPN_BATCH_C - (totP < NUM_FG ? totP : NUM_FG);
    __syncthreads();

    for (int s = base; s < end; s += TPB) {
        int k = s + tid;
        float l = (k < end) ? lab[k] : -1.f;
        int pos = (l == 1.f);
        int neg = (l == 0.f);
        unsigned ballp = __ballot_sync(FULL, pos);
        unsigned balln = __ballot_sync(FULL, neg);
        if (lane == 0) { s_wp[warp] = __popc(ballp); s_wn[warp] = __popc(balln); }
        __syncthreads();
        int wp = 0, wn = 0, totPb = 0, totNb = 0;
        #pragma unroll
        for (int v = 0; v < NW; v++) {
            int a2 = s_wp[v], b2 = s_wn[v];
            if (v < warp) { wp += a2; wn += b2; }
            totPb += a2; totNb += b2;
        }
        unsigned lm = (1u << lane) - 1u;
        int rp = runP + wp + __popc(ballp & lm) + 1;
        int rn = runN + wn + __popc(balln & lm) + 1;
        if (k < end) {
            if (pos && rp > NUM_FG) lab[k] = -1.f;
            if (neg && rn > numBg)  lab[k] = -1.f;
        }
        runP += totPb; runN += totNb;
        __syncthreads();
    }
}

// ---------------------------------------------------------------------------
extern "C" void kernel_launch(void* const* d_in, const int* in_sizes, int n_in,
                              void* d_out, int out_size) {
    const float* gt   = (const float*)d_in[0];
    const float* meta = (const float*)d_in[1];
    float* out = (float*)d_out;

    int G = in_sizes[0] / 4;
    if (G > MAX_G) G = MAX_G;
    int K  = in_sizes[2];
    int rc = K / A_NUM;
    int c  = (int)(sqrt((double)rc) + 0.5);
    int r  = rc / c;
    float inv_c = (float)(1.0 / (double)c);

    int dev = 0;
    cudaGetDevice(&dev);
    int nsm = 0;
    cudaDeviceGetAttribute(&nsm, cudaDevAttrMultiProcessorCount, dev);
    if (nsm <= 0) nsm = 148;
    int nblocks = 2 * nsm;               // 2 co-resident blocks per SM
    int nP1 = nblocks - G;               // dedicated phase-1 blocks
    if (nP1 < nblocks / 2) nP1 = nblocks / 2;
    if (nP1 > MAX_P1) nP1 = MAX_P1;
    int chunk = (K + nP1 - 1) / nP1;

    k_fused<<<nblocks, TPB>>>(gt, meta, out, K, r, c, G, nblocks, nP1, chunk, inv_c);
}